// round 1
// baseline (speedup 1.0000x reference)
#include <cuda_runtime.h>

// Problem constants (from reference): vol [B=4, D=160, H=192, W=160, C=1], trf [B,4,4]
#define BATCH 4
#define DD 160
#define HH 192
#define WW 160
#define VOX (DD * HH * WW)          // 4,915,200
#define TOTAL (BATCH * VOX)         // 19,660,800

__global__ __launch_bounds__(256) void st_affine_trilinear(
    const float* __restrict__ vol,   // [B, D, H, W]
    const float* __restrict__ trf,   // [B, 4, 4] row-major
    float* __restrict__ out)         // [B, D, H, W]
{
    const int idx = blockIdx.x * 256 + threadIdx.x;
    if (idx >= TOTAL) return;

    // Decompose index (constant divisors -> mul/shift)
    const int b   = idx / VOX;
    const int rem = idx - b * VOX;
    const int d   = rem / (HH * WW);
    const int r2  = rem - d * (HH * WW);
    const int h   = r2 / WW;
    const int w   = r2 - h * WW;

    // Affine rows (uniform per block: VOX % 256 == 0 so whole block shares b)
    const float* A = trf + b * 16;
    const float a00 = __ldg(A + 0), a01 = __ldg(A + 1), a02 = __ldg(A + 2), a03 = __ldg(A + 3);
    const float a10 = __ldg(A + 4), a11 = __ldg(A + 5), a12 = __ldg(A + 6), a13 = __ldg(A + 7);
    const float a20 = __ldg(A + 8), a21 = __ldg(A + 9), a22 = __ldg(A + 10), a23 = __ldg(A + 11);

    // Centered coordinates. loc = A[:3,:3] @ (p - c) + A[:3,3] + c
    const float cD = (DD - 1) * 0.5f, cH = (HH - 1) * 0.5f, cW = (WW - 1) * 0.5f;
    const float pd = (float)d - cD;
    const float ph = (float)h - cH;
    const float pw = (float)w - cW;

    const float ld = fmaf(a00, pd, fmaf(a01, ph, fmaf(a02, pw, a03))) + cD;
    const float lh = fmaf(a10, pd, fmaf(a11, ph, fmaf(a12, pw, a13))) + cH;
    const float lw = fmaf(a20, pd, fmaf(a21, ph, fmaf(a22, pw, a23))) + cW;

    // neuron-style clipping (exact reference semantics):
    //   loc0 = floor(loc); clipped = clip(loc, 0, max)
    //   i0 = clip(loc0, 0, max); i1 = clip(i0 + 1, 0, max)
    //   w0 = i1 - clipped (weight for corner i0); w1 = 1 - w0
    const float mD = (float)(DD - 1), mH = (float)(HH - 1), mW = (float)(WW - 1);

    float f0d = fminf(fmaxf(floorf(ld), 0.0f), mD);
    float f1d = fminf(f0d + 1.0f, mD);
    float w0d = f1d - fminf(fmaxf(ld, 0.0f), mD);
    float w1d = 1.0f - w0d;

    float f0h = fminf(fmaxf(floorf(lh), 0.0f), mH);
    float f1h = fminf(f0h + 1.0f, mH);
    float w0h = f1h - fminf(fmaxf(lh, 0.0f), mH);
    float w1h = 1.0f - w0h;

    float f0w = fminf(fmaxf(floorf(lw), 0.0f), mW);
    float f1w = fminf(f0w + 1.0f, mW);
    float w0w = f1w - fminf(fmaxf(lw, 0.0f), mW);
    float w1w = 1.0f - w0w;

    const int i0d = (int)f0d, i1d = (int)f1d;
    const int i0h = (int)f0h, i1h = (int)f1h;
    const int i0w = (int)f0w, i1w = (int)f1w;

    const float* v = vol + b * VOX;
    const int od0 = i0d * (HH * WW), od1 = i1d * (HH * WW);
    const int oh0 = i0h * WW,        oh1 = i1h * WW;

    // Issue all 8 loads back-to-back for MLP=8
    const float v000 = __ldg(v + od0 + oh0 + i0w);
    const float v001 = __ldg(v + od0 + oh0 + i1w);
    const float v010 = __ldg(v + od0 + oh1 + i0w);
    const float v011 = __ldg(v + od0 + oh1 + i1w);
    const float v100 = __ldg(v + od1 + oh0 + i0w);
    const float v101 = __ldg(v + od1 + oh0 + i1w);
    const float v110 = __ldg(v + od1 + oh1 + i0w);
    const float v111 = __ldg(v + od1 + oh1 + i1w);

    // Trilinear reduce: w first, then h, then d
    const float c00 = fmaf(v000, w0w, v001 * w1w);
    const float c01 = fmaf(v010, w0w, v011 * w1w);
    const float c10 = fmaf(v100, w0w, v101 * w1w);
    const float c11 = fmaf(v110, w0w, v111 * w1w);

    const float c0 = fmaf(c00, w0h, c01 * w1h);
    const float c1 = fmaf(c10, w0h, c11 * w1h);

    out[idx] = fmaf(c0, w0d, c1 * w1d);
}

extern "C" void kernel_launch(void* const* d_in, const int* in_sizes, int n_in,
                              void* d_out, int out_size) {
    const float* vol = (const float*)d_in[0];
    const float* trf = (const float*)d_in[1];
    float* out = (float*)d_out;
    const int blocks = (TOTAL + 255) / 256;
    st_affine_trilinear<<<blocks, 256>>>(vol, trf, out);
}

// round 2
// speedup vs baseline: 1.0796x; 1.0796x over previous
#include <cuda_runtime.h>

#define BATCH 4
#define DD 160
#define HH 192
#define WW 160
#define HW (HH * WW)
#define VOX (DD * HH * WW)          // 4,915,200
#define TOTAL (BATCH * VOX)         // 19,660,800
#define VPT 4                       // voxels per thread (along w)
#define TPB 256

__global__ __launch_bounds__(TPB) void st_affine_trilinear_v2(
    const float* __restrict__ vol,   // [B, D, H, W]
    const float* __restrict__ trf,   // [B, 4, 4]
    float* __restrict__ out)         // [B, D, H, W]
{
    const int tid  = blockIdx.x * TPB + threadIdx.x;
    const int idx4 = tid * VPT;                 // base linear output index
    // Decompose once per 4 voxels (w base is multiple of 4, stays within row)
    const int b   = idx4 / VOX;
    const int rem = idx4 - b * VOX;
    const int d   = rem / HW;
    const int r2  = rem - d * HW;
    const int h   = r2 / WW;
    const int w   = r2 - h * WW;

    const float* A = trf + b * 16;
    const float a00 = __ldg(A + 0), a01 = __ldg(A + 1), a02 = __ldg(A + 2), a03 = __ldg(A + 3);
    const float a10 = __ldg(A + 4), a11 = __ldg(A + 5), a12 = __ldg(A + 6), a13 = __ldg(A + 7);
    const float a20 = __ldg(A + 8), a21 = __ldg(A + 9), a22 = __ldg(A + 10), a23 = __ldg(A + 11);

    const float cD = (DD - 1) * 0.5f, cH = (HH - 1) * 0.5f, cW = (WW - 1) * 0.5f;
    const float pd = (float)d - cD;
    const float ph = (float)h - cH;
    const float pw = (float)w - cW;

    // Sample location at first voxel; subsequent voxels add column-2 coeffs
    const float ld0 = fmaf(a00, pd, fmaf(a01, ph, fmaf(a02, pw, a03))) + cD;
    const float lh0 = fmaf(a10, pd, fmaf(a11, ph, fmaf(a12, pw, a13))) + cH;
    const float lw0 = fmaf(a20, pd, fmaf(a21, ph, fmaf(a22, pw, a23))) + cW;

    const float mD = (float)(DD - 1), mH = (float)(HH - 1), mW = (float)(WW - 1);
    const float* v = vol + b * VOX;

    float res[VPT];

    #pragma unroll
    for (int j = 0; j < VPT; j++) {
        const float fj = (float)j;
        const float ld = fmaf(a02, fj, ld0);
        const float lh = fmaf(a12, fj, lh0);
        const float lw = fmaf(a22, fj, lw0);

        // Exact-equivalent cheap clip:
        //   t  = clip(l, 0, m)
        //   f0 = min(floor(t), m-1)   (i1 = i0 + 1 always valid)
        //   w0 = (f0 - t) + 1         (weight of corner i0, matches neuron semantics)
        const float td = fminf(fmaxf(ld, 0.0f), mD);
        const float th = fminf(fmaxf(lh, 0.0f), mH);
        const float tw = fminf(fmaxf(lw, 0.0f), mW);

        const float f0d = fminf(floorf(td), mD - 1.0f);
        const float f0h = fminf(floorf(th), mH - 1.0f);
        const float f0w = fminf(floorf(tw), mW - 1.0f);

        const float w0d = (f0d - td) + 1.0f;
        const float w0h = (f0h - th) + 1.0f;
        const float w0w = (f0w - tw) + 1.0f;

        const int i0d = (int)f0d;
        const int i0h = (int)f0h;
        const int i0w = (int)f0w;

        const int r00 = i0d * HW + i0h * WW;   // (d0,h0)
        const int r01 = r00 + WW;              // (d0,h1)
        const int r10 = r00 + HW;              // (d1,h0)
        const int r11 = r10 + WW;              // (d1,h1)

        const int c00 = r00 + i0w;
        const int c01 = r01 + i0w;
        const int c10 = r10 + i0w;
        const int c11 = r11 + i0w;

        // 8 gathers back-to-back (i1w = i0w+1 guaranteed by the clip scheme)
        const float v000 = __ldg(v + c00);
        const float v001 = __ldg(v + c00 + 1);
        const float v010 = __ldg(v + c01);
        const float v011 = __ldg(v + c01 + 1);
        const float v100 = __ldg(v + c10);
        const float v101 = __ldg(v + c10 + 1);
        const float v110 = __ldg(v + c11);
        const float v111 = __ldg(v + c11 + 1);

        // Lerp form: c = v1 + w0*(v0 - v1)
        const float e00 = fmaf(w0w, v000 - v001, v001);
        const float e01 = fmaf(w0w, v010 - v011, v011);
        const float e10 = fmaf(w0w, v100 - v101, v101);
        const float e11 = fmaf(w0w, v110 - v111, v111);

        const float e0 = fmaf(w0h, e00 - e01, e01);
        const float e1 = fmaf(w0h, e10 - e11, e11);

        res[j] = fmaf(w0d, e0 - e1, e1);
    }

    // Vector store: idx4 is 4-aligned -> 16B aligned
    float4 o;
    o.x = res[0]; o.y = res[1]; o.z = res[2]; o.w = res[3];
    *reinterpret_cast<float4*>(out + idx4) = o;
}

extern "C" void kernel_launch(void* const* d_in, const int* in_sizes, int n_in,
                              void* d_out, int out_size) {
    const float* vol = (const float*)d_in[0];
    const float* trf = (const float*)d_in[1];
    float* out = (float*)d_out;
    const int blocks = TOTAL / (TPB * VPT);   // 19200, exact
    st_affine_trilinear_v2<<<blocks, TPB>>>(vol, trf, out);
}

// round 3
// speedup vs baseline: 1.1478x; 1.0632x over previous
#include <cuda_runtime.h>

#define BATCH 4
#define DD 160
#define HH 192
#define WW 160
#define HW (HH * WW)
#define VOX (DD * HH * WW)          // 4,915,200
#define TOTAL (BATCH * VOX)         // 19,660,800
#define NROWS (BATCH * DD * HH)     // 122,880 (one warp per row)
#define TPB 256

// One warp per (b,d,h) row of W=160. Lane t handles w = t + 32*j, j=0..4.
// Gathers are warp-coalesced: consecutive lanes -> consecutive addresses.
__global__ __launch_bounds__(TPB) void st_affine_trilinear_v3(
    const float* __restrict__ vol,   // [B, D, H, W]
    const float* __restrict__ trf,   // [B, 4, 4]
    float* __restrict__ out)         // [B, D, H, W]
{
    const int gtid = blockIdx.x * TPB + threadIdx.x;
    const int row  = gtid >> 5;          // global warp id = row id
    const int lane = gtid & 31;

    // row -> (b, d, h)
    const int b  = row / (DD * HH);
    const int r  = row - b * (DD * HH);
    const int d  = r / HH;
    const int h  = r - d * HH;

    const float* A = trf + b * 16;
    const float a00 = __ldg(A + 0), a01 = __ldg(A + 1), a02 = __ldg(A + 2), a03 = __ldg(A + 3);
    const float a10 = __ldg(A + 4), a11 = __ldg(A + 5), a12 = __ldg(A + 6), a13 = __ldg(A + 7);
    const float a20 = __ldg(A + 8), a21 = __ldg(A + 9), a22 = __ldg(A + 10), a23 = __ldg(A + 11);

    const float cD = (DD - 1) * 0.5f, cH = (HH - 1) * 0.5f, cW = (WW - 1) * 0.5f;
    const float pd = (float)d - cD;
    const float ph = (float)h - cH;
    const float pw = (float)lane - cW;

    // Sample location at w = lane; each j adds 32 * column-2 coeffs
    float ld = fmaf(a00, pd, fmaf(a01, ph, fmaf(a02, pw, a03))) + cD;
    float lh = fmaf(a10, pd, fmaf(a11, ph, fmaf(a12, pw, a13))) + cH;
    float lw = fmaf(a20, pd, fmaf(a21, ph, fmaf(a22, pw, a23))) + cW;
    const float sd = 32.0f * a02;
    const float sh = 32.0f * a12;
    const float sw = 32.0f * a22;

    const float mD = (float)(DD - 1), mH = (float)(HH - 1), mW = (float)(WW - 1);
    const float* v = vol + b * VOX;
    float* o = out + row * WW + lane;

    #pragma unroll
    for (int j = 0; j < 5; j++) {
        // Exact-equivalent cheap clip (matches neuron semantics):
        //   t = clip(l,0,m); f0 = min(floor(t), m-1); i1 = i0+1; w0 = (f0-t)+1
        const float td = fminf(fmaxf(ld, 0.0f), mD);
        const float th = fminf(fmaxf(lh, 0.0f), mH);
        const float tw = fminf(fmaxf(lw, 0.0f), mW);

        const float f0d = fminf(floorf(td), mD - 1.0f);
        const float f0h = fminf(floorf(th), mH - 1.0f);
        const float f0w = fminf(floorf(tw), mW - 1.0f);

        const float w0d = (f0d - td) + 1.0f;
        const float w0h = (f0h - th) + 1.0f;
        const float w0w = (f0w - tw) + 1.0f;

        const int i0d = (int)f0d;
        const int i0h = (int)f0h;
        const int i0w = (int)f0w;

        const int c00 = i0d * HW + i0h * WW + i0w;   // (d0,h0)
        const int c01 = c00 + WW;                    // (d0,h1)
        const int c10 = c00 + HW;                    // (d1,h0)
        const int c11 = c10 + WW;                    // (d1,h1)

        // 8 coalesced gathers back-to-back
        const float v000 = __ldg(v + c00);
        const float v001 = __ldg(v + c00 + 1);
        const float v010 = __ldg(v + c01);
        const float v011 = __ldg(v + c01 + 1);
        const float v100 = __ldg(v + c10);
        const float v101 = __ldg(v + c10 + 1);
        const float v110 = __ldg(v + c11);
        const float v111 = __ldg(v + c11 + 1);

        const float e00 = fmaf(w0w, v000 - v001, v001);
        const float e01 = fmaf(w0w, v010 - v011, v011);
        const float e10 = fmaf(w0w, v100 - v101, v101);
        const float e11 = fmaf(w0w, v110 - v111, v111);

        const float e0 = fmaf(w0h, e00 - e01, e01);
        const float e1 = fmaf(w0h, e10 - e11, e11);

        o[j * 32] = fmaf(w0d, e0 - e1, e1);

        // advance sample location by 32 voxels along w
        ld += sd;
        lh += sh;
        lw += sw;
    }
}

extern "C" void kernel_launch(void* const* d_in, const int* in_sizes, int n_in,
                              void* d_out, int out_size) {
    const float* vol = (const float*)d_in[0];
    const float* trf = (const float*)d_in[1];
    float* out = (float*)d_out;
    const int blocks = (NROWS * 32) / TPB;   // 15360, exact
    st_affine_trilinear_v3<<<blocks, TPB>>>(vol, trf, out);
}

// round 4
// speedup vs baseline: 1.2599x; 1.0976x over previous
#include <cuda_runtime.h>

#define BATCH 4
#define DD 160
#define HH 192
#define WW 160
#define HW (HH * WW)                 // 30720
#define VOX (DD * HH * WW)           // 4,915,200
#define NROWS (BATCH * DD * HH)      // 122,880
#define TPB 256

// One warp per (b,d,h) row. Lane handles w-pairs: w0 = 64*j + 2*lane, w1 = w0+1.
// j = 0,1 full warp; j = 2 lanes 0..15 (WW=160).
__global__ __launch_bounds__(TPB) void st_affine_trilinear_v4(
    const float* __restrict__ vol,   // [B, D, H, W]
    const float* __restrict__ trf,   // [B, 4, 4]
    float* __restrict__ out)         // [B, D, H, W]
{
    const int gtid = blockIdx.x * TPB + threadIdx.x;
    const int row  = gtid >> 5;
    const int lane = gtid & 31;

    const int b  = row / (DD * HH);
    const int r  = row - b * (DD * HH);
    const int d  = r / HH;
    const int h  = r - d * HH;

    const float* A = trf + b * 16;
    const float a00 = __ldg(A + 0), a01 = __ldg(A + 1), a02 = __ldg(A + 2), a03 = __ldg(A + 3);
    const float a10 = __ldg(A + 4), a11 = __ldg(A + 5), a12 = __ldg(A + 6), a13 = __ldg(A + 7);
    const float a20 = __ldg(A + 8), a21 = __ldg(A + 9), a22 = __ldg(A + 10), a23 = __ldg(A + 11);

    const float cD = (DD - 1) * 0.5f, cH = (HH - 1) * 0.5f, cW = (WW - 1) * 0.5f;
    const float pd = (float)d - cD;
    const float ph = (float)h - cH;

    const float mD = (float)(DD - 1), mH = (float)(HH - 1), mW = (float)(WW - 1);
    const float* v = vol + b * VOX;
    float* orow = out + row * WW;

    #pragma unroll
    for (int j = 0; j < 3; j++) {
        const int w0 = 64 * j + 2 * lane;
        if (j == 2 && lane >= 16) break;          // w0 >= 160

        const float pw0 = (float)w0 - cW;

        // ---- voxel 0 coordinates / indices / weights ----
        const float ld0 = fmaf(a00, pd, fmaf(a01, ph, fmaf(a02, pw0, a03))) + cD;
        const float lh0 = fmaf(a10, pd, fmaf(a11, ph, fmaf(a12, pw0, a13))) + cH;
        const float lw0 = fmaf(a20, pd, fmaf(a21, ph, fmaf(a22, pw0, a23))) + cW;

        const float td0 = fminf(fmaxf(ld0, 0.0f), mD);
        const float th0 = fminf(fmaxf(lh0, 0.0f), mH);
        const float tw0 = fminf(fmaxf(lw0, 0.0f), mW);
        const float f0d0 = fminf(floorf(td0), mD - 1.0f);
        const float f0h0 = fminf(floorf(th0), mH - 1.0f);
        const float f0w0 = fminf(floorf(tw0), mW - 1.0f);
        const float w0d0 = (f0d0 - td0) + 1.0f;
        const float w0h0 = (f0h0 - th0) + 1.0f;
        const float w0w0 = (f0w0 - tw0) + 1.0f;
        // flat corner index via exact fp32 integer arithmetic (< 2^23)
        const int c0 = (int)(fmaf(f0d0, (float)HW, fmaf(f0h0, (float)WW, f0w0)));
        const int i0w0 = (int)f0w0;

        // ---- voxel 1 coordinates / indices / weights ----
        const float ld1 = ld0 + a02;
        const float lh1 = lh0 + a12;
        const float lw1 = lw0 + a22;

        const float td1 = fminf(fmaxf(ld1, 0.0f), mD);
        const float th1 = fminf(fmaxf(lh1, 0.0f), mH);
        const float tw1 = fminf(fmaxf(lw1, 0.0f), mW);
        const float f0d1 = fminf(floorf(td1), mD - 1.0f);
        const float f0h1 = fminf(floorf(th1), mH - 1.0f);
        const float f0w1 = fminf(floorf(tw1), mW - 1.0f);
        const float w0d1 = (f0d1 - td1) + 1.0f;
        const float w0h1 = (f0h1 - th1) + 1.0f;
        const float w0w1 = (f0w1 - tw1) + 1.0f;
        const int c1 = (int)(fmaf(f0d1, (float)HW, fmaf(f0h1, (float)WW, f0w1)));

        // ---- shared aligned 4-element window [e .. e+3] on voxel0's rows ----
        const int e  = c0 & ~1;                    // 8B aligned; rowbase even, so
        const int k0 = c0 - e;                     // k0 in {0,1}
        const int k1 = c1 - e;                     // in {0,1,2} when shareable
        // qb would read w-indices 160,161 only when i0w0==158 (then qb unused):
        const int qbs = (i0w0 < 158) ? 1 : 0;      // qb pointer step in float2 units

        const float2* p = reinterpret_cast<const float2*>(v + e);
        const float2 qa00 = __ldg(p);
        const float2 qb00 = __ldg(p + qbs);
        const float2 qa01 = __ldg(p + (WW / 2));
        const float2 qb01 = __ldg(p + (WW / 2) + qbs);
        const float2 qa10 = __ldg(p + (HW / 2));
        const float2 qb10 = __ldg(p + (HW / 2) + qbs);
        const float2 qa11 = __ldg(p + ((HW + WW) / 2));
        const float2 qb11 = __ldg(p + ((HW + WW) / 2) + qbs);

        // ---- voxel 0 corner values (k0 selects within window) ----
        const bool o0 = (k0 != 0);
        const float x00a = o0 ? qa00.y : qa00.x, x00b = o0 ? qb00.x : qa00.y;
        const float x01a = o0 ? qa01.y : qa01.x, x01b = o0 ? qb01.x : qa01.y;
        const float x10a = o0 ? qa10.y : qa10.x, x10b = o0 ? qb10.x : qa10.y;
        const float x11a = o0 ? qa11.y : qa11.x, x11b = o0 ? qb11.x : qa11.y;

        // ---- voxel 1 corner values ----
        float y00a, y00b, y01a, y01b, y10a, y10b, y11a, y11b;
        if ((unsigned)k1 <= 2u) {
            const bool s1 = (k1 >= 1), s2 = (k1 >= 2);
            y00a = s2 ? qb00.x : (s1 ? qa00.y : qa00.x);
            y00b = s2 ? qb00.y : (s1 ? qb00.x : qa00.y);
            y01a = s2 ? qb01.x : (s1 ? qa01.y : qa01.x);
            y01b = s2 ? qb01.y : (s1 ? qb01.x : qa01.y);
            y10a = s2 ? qb10.x : (s1 ? qa10.y : qa10.x);
            y10b = s2 ? qb10.y : (s1 ? qb10.x : qa10.y);
            y11a = s2 ? qb11.x : (s1 ? qa11.y : qa11.x);
            y11b = s2 ? qb11.y : (s1 ? qb11.x : qa11.y);
        } else {
            // rare fixup: voxel1's rows differ or window overflow
            y00a = __ldg(v + c1);
            y00b = __ldg(v + c1 + 1);
            y01a = __ldg(v + c1 + WW);
            y01b = __ldg(v + c1 + WW + 1);
            y10a = __ldg(v + c1 + HW);
            y10b = __ldg(v + c1 + HW + 1);
            y11a = __ldg(v + c1 + HW + WW);
            y11b = __ldg(v + c1 + HW + WW + 1);
        }

        // ---- trilinear both voxels ----
        float e00 = fmaf(w0w0, x00a - x00b, x00b);
        float e01 = fmaf(w0w0, x01a - x01b, x01b);
        float e10 = fmaf(w0w0, x10a - x10b, x10b);
        float e11 = fmaf(w0w0, x11a - x11b, x11b);
        float eh0 = fmaf(w0h0, e00 - e01, e01);
        float eh1 = fmaf(w0h0, e10 - e11, e11);
        const float r0 = fmaf(w0d0, eh0 - eh1, eh1);

        float g00 = fmaf(w0w1, y00a - y00b, y00b);
        float g01 = fmaf(w0w1, y01a - y01b, y01b);
        float g10 = fmaf(w0w1, y10a - y10b, y10b);
        float g11 = fmaf(w0w1, y11a - y11b, y11b);
        float gh0 = fmaf(w0h1, g00 - g01, g01);
        float gh1 = fmaf(w0h1, g10 - g11, g11);
        const float r1 = fmaf(w0d1, gh0 - gh1, gh1);

        float2 res;
        res.x = r0;
        res.y = r1;
        *reinterpret_cast<float2*>(orow + w0) = res;
    }
}

extern "C" void kernel_launch(void* const* d_in, const int* in_sizes, int n_in,
                              void* d_out, int out_size) {
    const float* vol = (const float*)d_in[0];
    const float* trf = (const float*)d_in[1];
    float* out = (float*)d_out;
    const int blocks = (NROWS * 32) / TPB;   // 15360
    st_affine_trilinear_v4<<<blocks, TPB>>>(vol, trf, out);
}

// round 5
// speedup vs baseline: 1.3422x; 1.0654x over previous
#include <cuda_runtime.h>

#define BATCH 4
#define DD 160
#define HH 192
#define WW 160
#define HW (HH * WW)                 // 30720
#define VOX (DD * HH * WW)           // 4,915,200
#define TOTAL (BATCH * VOX)          // 19,660,800
#define NPAIR (TOTAL / 2)            // 9,830,400
#define PPROW (WW / 2)               // 80 pairs per row
#define TPB 256

// One w-pair per thread: g -> (row, pair). Shared aligned float2-window gather.
__global__ __launch_bounds__(TPB, 6) void st_affine_trilinear_v5(
    const float* __restrict__ vol,   // [B, D, H, W]
    const float* __restrict__ trf,   // [B, 4, 4]
    float* __restrict__ out)         // [B, D, H, W]
{
    const int g = blockIdx.x * TPB + threadIdx.x;

    const int row = g / PPROW;
    const int w0  = (g - row * PPROW) * 2;

    const int b  = row / (DD * HH);
    const int r  = row - b * (DD * HH);
    const int d  = r / HH;
    const int h  = r - d * HH;

    const float* A = trf + b * 16;
    const float a00 = A[0], a01 = A[1], a02 = A[2],  a03 = A[3];
    const float a10 = A[4], a11 = A[5], a12 = A[6],  a13 = A[7];
    const float a20 = A[8], a21 = A[9], a22 = A[10], a23 = A[11];

    const float cD = (DD - 1) * 0.5f, cH = (HH - 1) * 0.5f, cW = (WW - 1) * 0.5f;
    const float pd  = (float)d - cD;
    const float ph  = (float)h - cH;
    const float pw0 = (float)w0 - cW;

    const float mD = (float)(DD - 1), mH = (float)(HH - 1), mW = (float)(WW - 1);
    const float* v = vol + b * VOX;

    // ---- voxel 0 ----
    const float ld0 = fmaf(a00, pd, fmaf(a01, ph, fmaf(a02, pw0, a03))) + cD;
    const float lh0 = fmaf(a10, pd, fmaf(a11, ph, fmaf(a12, pw0, a13))) + cH;
    const float lw0 = fmaf(a20, pd, fmaf(a21, ph, fmaf(a22, pw0, a23))) + cW;

    const float td0 = fminf(fmaxf(ld0, 0.0f), mD);
    const float th0 = fminf(fmaxf(lh0, 0.0f), mH);
    const float tw0 = fminf(fmaxf(lw0, 0.0f), mW);
    const float f0d0 = fminf(floorf(td0), mD - 1.0f);
    const float f0h0 = fminf(floorf(th0), mH - 1.0f);
    const float f0w0 = fminf(floorf(tw0), mW - 1.0f);
    const float w0d0 = (f0d0 - td0) + 1.0f;
    const float w0h0 = (f0h0 - th0) + 1.0f;
    const float w0w0 = (f0w0 - tw0) + 1.0f;
    const int c0   = (int)(fmaf(f0d0, (float)HW, fmaf(f0h0, (float)WW, f0w0)));
    const int i0w0 = (int)f0w0;

    // ---- voxel 1 ----
    const float ld1 = ld0 + a02;
    const float lh1 = lh0 + a12;
    const float lw1 = lw0 + a22;

    const float td1 = fminf(fmaxf(ld1, 0.0f), mD);
    const float th1 = fminf(fmaxf(lh1, 0.0f), mH);
    const float tw1 = fminf(fmaxf(lw1, 0.0f), mW);
    const float f0d1 = fminf(floorf(td1), mD - 1.0f);
    const float f0h1 = fminf(floorf(th1), mH - 1.0f);
    const float f0w1 = fminf(floorf(tw1), mW - 1.0f);
    const float w0d1 = (f0d1 - td1) + 1.0f;
    const float w0h1 = (f0h1 - th1) + 1.0f;
    const float w0w1 = (f0w1 - tw1) + 1.0f;
    const int c1 = (int)(fmaf(f0d1, (float)HW, fmaf(f0h1, (float)WW, f0w1)));

    // ---- shared aligned float2 window [e .. e+3] on voxel0's rows ----
    const int e  = c0 & ~1;
    const int k0 = c0 - e;                     // {0,1}
    const int k1 = c1 - e;                     // {0,1,2} when shareable
    const int qbs = (i0w0 < 158) ? 1 : 0;      // avoid reading past row end

    const float2* p = reinterpret_cast<const float2*>(v + e);
    const float2 qa00 = __ldg(p);
    const float2 qb00 = __ldg(p + qbs);
    const float2 qa01 = __ldg(p + (WW / 2));
    const float2 qb01 = __ldg(p + (WW / 2) + qbs);
    const float2 qa10 = __ldg(p + (HW / 2));
    const float2 qb10 = __ldg(p + (HW / 2) + qbs);
    const float2 qa11 = __ldg(p + ((HW + WW) / 2));
    const float2 qb11 = __ldg(p + ((HW + WW) / 2) + qbs);

    // ---- voxel 0 corner values ----
    const bool o0 = (k0 != 0);
    const float x00a = o0 ? qa00.y : qa00.x, x00b = o0 ? qb00.x : qa00.y;
    const float x01a = o0 ? qa01.y : qa01.x, x01b = o0 ? qb01.x : qa01.y;
    const float x10a = o0 ? qa10.y : qa10.x, x10b = o0 ? qb10.x : qa10.y;
    const float x11a = o0 ? qa11.y : qa11.x, x11b = o0 ? qb11.x : qa11.y;

    float e00 = fmaf(w0w0, x00a - x00b, x00b);
    float e01 = fmaf(w0w0, x01a - x01b, x01b);
    float e10 = fmaf(w0w0, x10a - x10b, x10b);
    float e11 = fmaf(w0w0, x11a - x11b, x11b);
    float eh0 = fmaf(w0h0, e00 - e01, e01);
    float eh1 = fmaf(w0h0, e10 - e11, e11);
    const float r0 = fmaf(w0d0, eh0 - eh1, eh1);

    // ---- voxel 1 corner values ----
    float y00a, y00b, y01a, y01b, y10a, y10b, y11a, y11b;
    if ((unsigned)k1 <= 2u) {
        const bool s1 = (k1 >= 1), s2 = (k1 >= 2);
        y00a = s2 ? qb00.x : (s1 ? qa00.y : qa00.x);
        y00b = s2 ? qb00.y : (s1 ? qb00.x : qa00.y);
        y01a = s2 ? qb01.x : (s1 ? qa01.y : qa01.x);
        y01b = s2 ? qb01.y : (s1 ? qb01.x : qa01.y);
        y10a = s2 ? qb10.x : (s1 ? qa10.y : qa10.x);
        y10b = s2 ? qb10.y : (s1 ? qb10.x : qa10.y);
        y11a = s2 ? qb11.x : (s1 ? qa11.y : qa11.x);
        y11b = s2 ? qb11.y : (s1 ? qb11.x : qa11.y);
    } else {
        y00a = __ldg(v + c1);
        y00b = __ldg(v + c1 + 1);
        y01a = __ldg(v + c1 + WW);
        y01b = __ldg(v + c1 + WW + 1);
        y10a = __ldg(v + c1 + HW);
        y10b = __ldg(v + c1 + HW + 1);
        y11a = __ldg(v + c1 + HW + WW);
        y11b = __ldg(v + c1 + HW + WW + 1);
    }

    float g00 = fmaf(w0w1, y00a - y00b, y00b);
    float g01 = fmaf(w0w1, y01a - y01b, y01b);
    float g10 = fmaf(w0w1, y10a - y10b, y10b);
    float g11 = fmaf(w0w1, y11a - y11b, y11b);
    float gh0 = fmaf(w0h1, g00 - g01, g01);
    float gh1 = fmaf(w0h1, g10 - g11, g11);
    const float r1 = fmaf(w0d1, gh0 - gh1, gh1);

    float2 res;
    res.x = r0;
    res.y = r1;
    *reinterpret_cast<float2*>(out + row * WW + w0) = res;
}

extern "C" void kernel_launch(void* const* d_in, const int* in_sizes, int n_in,
                              void* d_out, int out_size) {
    const float* vol = (const float*)d_in[0];
    const float* trf = (const float*)d_in[1];
    float* out = (float*)d_out;
    const int blocks = NPAIR / TPB;   // 38400, exact
    st_affine_trilinear_v5<<<blocks, TPB>>>(vol, trf, out);
}